// round 14
// baseline (speedup 1.0000x reference)
#include <cuda_runtime.h>
#include <cuda_bf16.h>
#include <stdint.h>

// ---------------------------------------------------------------------------
// N=50000, D=128, GCN out=512, H=256, E=800000. edge_index int32.
// h1 = leaky(xs @ (W_gcn@W1) + (b_gcn@W1 + b1)),  xs = S @ x.
// Graph agg: 4 interleaved linked-list chains per node (4x spine MLP).
// 3 GEMMs (K=128,256,256), mma.sync bf16x3 split, W_out dot fused in GEMM3.
// ---------------------------------------------------------------------------
#define MAXN  50000
#define MAXNP 50048      // multiple of 128; padded rows are zero
#define MAXE  800000
#define DIN   128
#define DGCN  512
#define HDIM  256
#define DIV_UP(a, b) (((a) + (b) - 1) / (b))

typedef __nv_bfloat16 bf16;

// ---- scratch (device globals; zero-initialized at module load) ----
__device__ bf16  g_xs_h[(size_t)MAXNP * DIN],  g_xs_l[(size_t)MAXNP * DIN];
__device__ bf16  g_h1_h[(size_t)MAXNP * HDIM], g_h1_l[(size_t)MAXNP * HDIM];
__device__ bf16  g_h2_h[(size_t)MAXNP * HDIM], g_h2_l[(size_t)MAXNP * HDIM];
// combined + split weights [NOUT, K]
__device__ bf16  g_Wc_h[HDIM * DIN],  g_Wc_l[HDIM * DIN];   // (W_gcn@W1)^T split
__device__ float g_bc[HDIM];                                 // b_gcn@W1 + b1
__device__ bf16  g_W2_h[HDIM * HDIM], g_W2_l[HDIM * HDIM];
__device__ bf16  g_W3_h[HDIM * HDIM], g_W3_l[HDIM * HDIM];
// graph: 4 interleaved chains per node
__device__ int g_head[4 * MAXN], g_cnt[MAXN], g_link[MAXE];

__device__ __forceinline__ float leaky(float v) { return v > 0.f ? v : 0.1f * v; }

__device__ __forceinline__ uint32_t smem_u32(const void* p) {
    uint32_t a;
    asm("{ .reg .u64 t; cvta.to.shared.u64 t, %1; cvt.u32.u64 %0, t; }"
        : "=r"(a) : "l"(p));
    return a;
}

// smem tile: 128 rows x 64 bytes (32 bf16); chunk = 16B; swizzle keeps
// ldmatrix 8-lane phases and cp.async writes conflict-free.
__device__ __forceinline__ uint32_t swz(int row, int chunk) {
    return (uint32_t)(row * 64 + ((chunk ^ ((row ^ (row >> 2)) & 3)) * 16));
}

#define LDSM4(r, addr)                                                         \
    asm volatile("ldmatrix.sync.aligned.m8n8.x4.shared.b16 {%0,%1,%2,%3}, [%4];" \
                 : "=r"((r)[0]), "=r"((r)[1]), "=r"((r)[2]), "=r"((r)[3])      \
                 : "r"(addr))

#define MMA16(c, av, b0, b1)                                                   \
    asm volatile("mma.sync.aligned.m16n8k16.row.col.f32.bf16.bf16.f32 "        \
                 "{%0,%1,%2,%3}, {%4,%5,%6,%7}, {%8,%9}, {%0,%1,%2,%3};"       \
                 : "+f"((c)[0]), "+f"((c)[1]), "+f"((c)[2]), "+f"((c)[3])      \
                 : "r"((av)[0]), "r"((av)[1]), "r"((av)[2]), "r"((av)[3]),     \
                   "r"(b0), "r"(b1))

// ---------------------------------------------------------------------------
// bf16x3 warp-MMA GEMM: C[M,NOUT] = split(A[M,K]) @ split(B[NOUT,K])^T
// Block 128x128, BK=32, 256 thr (8 warps, 2x4), warp tile 64x32.
// DOTOUT: fuse out[r] += sum_col leaky(C[r,col]+bias[col]) * wout[col].
// ---------------------------------------------------------------------------
template <int K, bool LEAKY, bool DOTOUT>
__global__ __launch_bounds__(256, 2)
void mma_gemm(const bf16* __restrict__ Ah, const bf16* __restrict__ Al,
              const bf16* __restrict__ Bh, const bf16* __restrict__ Bl,
              const float* __restrict__ bias,
              bf16* __restrict__ Ch, bf16* __restrict__ Cl,
              const float* __restrict__ wout, float* __restrict__ dout,
              int NOUT, int MREAL) {
    extern __shared__ char sm[];
    const uint32_t sbase = smem_u32(sm);

    const int tid = threadIdx.x;
    const int lane = tid & 31, wid = tid >> 5;
    const int wm = wid >> 2, wn = wid & 3;        // 2 x 4 warp grid
    const int brow = blockIdx.y * 128;
    const int bcol = blockIdx.x * 128;

    float acc[4][4][4] = {};
    constexpr int NST = K / 32;

    // per-thread cp.async slots (2 chunks x 4 tiles), hoisted
    const int idx0 = tid * 2;                     // 0..510 within tile
    const int row0 = idx0 >> 2, c0 = idx0 & 3;
    const int row1 = (idx0 + 1) >> 2, c1 = (idx0 + 1) & 3;
    const uint32_t so0 = swz(row0, c0), so1 = swz(row1, c1);

    auto load_stage = [&](int s, int buf) {
        const int kofs = s * 32;
        const uint32_t sb = sbase + buf * 32768;
        const bf16* srcs[4] = {
            Ah + (size_t)brow * K + kofs, Al + (size_t)brow * K + kofs,
            Bh + (size_t)bcol * K + kofs, Bl + (size_t)bcol * K + kofs};
#pragma unroll
        for (int tile = 0; tile < 4; ++tile) {
            const bf16* base = srcs[tile];
            const uint32_t d = sb + tile * 8192;
            asm volatile("cp.async.cg.shared.global [%0], [%1], 16;"
                         :: "r"(d + so0), "l"(base + (size_t)row0 * K + c0 * 8));
            asm volatile("cp.async.cg.shared.global [%0], [%1], 16;"
                         :: "r"(d + so1), "l"(base + (size_t)row1 * K + c1 * 8));
        }
        asm volatile("cp.async.commit_group;" ::: "memory");
    };

    // ldmatrix address pieces (constant per thread across stages)
    const int arow_base = wm * 64 + (lane & 7) + ((lane >> 3) & 1) * 8;
    const int ach_half = lane >> 4;                       // 0/1
    const int brow_base = wn * 32 + ((lane >> 4) & 1) * 8 + (lane & 7);
    const int bch_half = (lane >> 3) & 1;                 // 0/1

    auto do_compute = [&](int buf) {
        const uint32_t sb = sbase + buf * 32768;
        const uint32_t Ahb = sb, Alb = sb + 8192;
        const uint32_t Bhb = sb + 16384, Blb = sb + 24576;
#pragma unroll
        for (int ks = 0; ks < 2; ++ks) {
            const int ach = ks * 2 + ach_half;
            const int bch = ks * 2 + bch_half;
            uint32_t a[4][4], bh[4][2], bl[4][2];
#pragma unroll
            for (int mi = 0; mi < 4; ++mi)
                LDSM4(a[mi], Ahb + swz(arow_base + mi * 16, ach));
#pragma unroll
            for (int p = 0; p < 2; ++p) {
                uint32_t r[4];
                LDSM4(r, Bhb + swz(brow_base + p * 16, bch));
                bh[p * 2][0] = r[0]; bh[p * 2][1] = r[1];
                bh[p * 2 + 1][0] = r[2]; bh[p * 2 + 1][1] = r[3];
            }
            // t0: Ah x Bh
#pragma unroll
            for (int mi = 0; mi < 4; ++mi)
#pragma unroll
                for (int ni = 0; ni < 4; ++ni)
                    MMA16(acc[mi][ni], a[mi], bh[ni][0], bh[ni][1]);
#pragma unroll
            for (int p = 0; p < 2; ++p) {
                uint32_t r[4];
                LDSM4(r, Blb + swz(brow_base + p * 16, bch));
                bl[p * 2][0] = r[0]; bl[p * 2][1] = r[1];
                bl[p * 2 + 1][0] = r[2]; bl[p * 2 + 1][1] = r[3];
            }
            // t1: Ah x Bl  (reuse a)
#pragma unroll
            for (int mi = 0; mi < 4; ++mi)
#pragma unroll
                for (int ni = 0; ni < 4; ++ni)
                    MMA16(acc[mi][ni], a[mi], bl[ni][0], bl[ni][1]);
            // Al fragments (overwrite a)
#pragma unroll
            for (int mi = 0; mi < 4; ++mi)
                LDSM4(a[mi], Alb + swz(arow_base + mi * 16, ach));
            // t2: Al x Bh  (reuse bh)
#pragma unroll
            for (int mi = 0; mi < 4; ++mi)
#pragma unroll
                for (int ni = 0; ni < 4; ++ni)
                    MMA16(acc[mi][ni], a[mi], bh[ni][0], bh[ni][1]);
        }
    };

    // 3-stage circular pipeline, loads run 2 stages ahead
    load_stage(0, 0);
    if (NST > 1) load_stage(1, 1);
    for (int s = 0; s < NST; ++s) {
        if (s + 1 < NST)
            asm volatile("cp.async.wait_group 1;" ::: "memory");
        else
            asm volatile("cp.async.wait_group 0;" ::: "memory");
        __syncthreads();
        if (s + 2 < NST) load_stage(s + 2, (s + 2) % 3);
        do_compute(s % 3);
    }

    // ---- epilogue ----
    if (DOTOUT) {
        float rs[4][2] = {};   // per (mi, h) partial row dots
#pragma unroll
        for (int mi = 0; mi < 4; ++mi) {
#pragma unroll
            for (int ni = 0; ni < 4; ++ni) {
                const int col = bcol + wn * 32 + ni * 8 + (lane & 3) * 2;
                const float2 bb = *(const float2*)&bias[col];
                const float2 wo = *(const float2*)&wout[col];
#pragma unroll
                for (int h = 0; h < 2; ++h) {
                    float v0 = acc[mi][ni][h * 2 + 0] + bb.x;
                    float v1 = acc[mi][ni][h * 2 + 1] + bb.y;
                    if (LEAKY) { v0 = leaky(v0); v1 = leaky(v1); }
                    rs[mi][h] += v0 * wo.x + v1 * wo.y;
                }
            }
        }
#pragma unroll
        for (int mi = 0; mi < 4; ++mi)
#pragma unroll
            for (int h = 0; h < 2; ++h) {
                rs[mi][h] += __shfl_xor_sync(0xFFFFFFFFu, rs[mi][h], 1);
                rs[mi][h] += __shfl_xor_sync(0xFFFFFFFFu, rs[mi][h], 2);
            }
        if ((lane & 3) == 0) {
            const int rbase = brow + wm * 64 + (lane >> 2);
#pragma unroll
            for (int mi = 0; mi < 4; ++mi)
#pragma unroll
                for (int h = 0; h < 2; ++h) {
                    const int r = rbase + mi * 16 + h * 8;
                    if (r < MREAL) atomicAdd(&dout[r], rs[mi][h]);
                }
        }
    } else {
#pragma unroll
        for (int mi = 0; mi < 4; ++mi) {
            const int r0 = brow + wm * 64 + mi * 16 + (lane >> 2);
#pragma unroll
            for (int ni = 0; ni < 4; ++ni) {
                const int col = bcol + wn * 32 + ni * 8 + (lane & 3) * 2;
                const float2 bb = *(const float2*)&bias[col];
#pragma unroll
                for (int h = 0; h < 2; ++h) {
                    const int r = r0 + h * 8;
                    float v0 = acc[mi][ni][h * 2 + 0] + bb.x;
                    float v1 = acc[mi][ni][h * 2 + 1] + bb.y;
                    if (LEAKY) { v0 = leaky(v0); v1 = leaky(v1); }
                    const __nv_bfloat162 hv = __floats2bfloat162_rn(v0, v1);
                    *(__nv_bfloat162*)&Ch[(size_t)r * NOUT + col] = hv;
                    const float l0 = v0 - __bfloat162float(hv.x);
                    const float l1 = v1 - __bfloat162float(hv.y);
                    *(__nv_bfloat162*)&Cl[(size_t)r * NOUT + col] =
                        __floats2bfloat162_rn(l0, l1);
                }
            }
        }
    }
}

// ---------------------------------------------------------------------------
// Prep (one kernel): W2/W3 transpose+split, out=b_out, heads=-1, cnt=0
// ---------------------------------------------------------------------------
#define PW0 (HDIM * HDIM)
#define PW1 (2 * HDIM * HDIM)
__global__ void prep_all(const float* __restrict__ W2, const float* __restrict__ W3,
                         const float* __restrict__ bout, float* __restrict__ out,
                         int n) {
    const int g = blockIdx.x * blockDim.x + threadIdx.x;
    if (g >= PW1) {
        const int i = g - PW1;
        if (i < n) {
            out[i] = bout[0];
            g_cnt[i] = 0;
            g_head[4 * i + 0] = -1;
            g_head[4 * i + 1] = -1;
            g_head[4 * i + 2] = -1;
            g_head[4 * i + 3] = -1;
        }
        return;
    }
    const float* W; bf16 *Th, *Tl; int idx;
    if (g < PW0) { W = W2; Th = g_W2_h; Tl = g_W2_l; idx = g; }
    else         { W = W3; Th = g_W3_h; Tl = g_W3_l; idx = g - PW0; }
    const int n2 = idx / HDIM, k = idx % HDIM;
    const float v = W[(size_t)k * HDIM + n2];
    const bf16 h = __float2bfloat16(v);
    Th[idx] = h;
    Tl[idx] = __float2bfloat16(v - __bfloat162float(h));
}

// ---------------------------------------------------------------------------
// Wc = W_gcn @ W1 (blocks 0..127, k-row cached in smem) ; bc (block 128)
// ---------------------------------------------------------------------------
__global__ __launch_bounds__(256)
void wc_bc_kernel(const float* __restrict__ Wg, const float* __restrict__ W1,
                  const float* __restrict__ bg, const float* __restrict__ b1) {
    const int n = threadIdx.x;         // 0..255
    if (blockIdx.x == DIN) {           // bc = b_gcn @ W1 + b1
        float acc = b1[n];
#pragma unroll 8
        for (int j = 0; j < DGCN; ++j)
            acc += bg[j] * W1[(size_t)j * HDIM + n];
        g_bc[n] = acc;
        return;
    }
    __shared__ float row[DGCN];
    const int k = blockIdx.x;          // 0..127
    row[n] = Wg[(size_t)k * DGCN + n];
    row[n + 256] = Wg[(size_t)k * DGCN + n + 256];
    __syncthreads();
    float acc = 0.f;
#pragma unroll 8
    for (int j = 0; j < DGCN; ++j)
        acc += row[j] * W1[(size_t)j * HDIM + n];
    const bf16 h = __float2bfloat16(acc);
    g_Wc_h[n * DIN + k] = h;
    g_Wc_l[n * DIN + k] = __float2bfloat16(acc - __bfloat162float(h));
}

// ---------------------------------------------------------------------------
// 4-chain bucket scatter: chain (d, e&3); cnt[dst]++.
// ---------------------------------------------------------------------------
__global__ void scatter_ll(const int* __restrict__ src,
                           const int* __restrict__ dst, int E, int n) {
    int e = blockIdx.x * blockDim.x + threadIdx.x;
    if (e < E) {
        int d = dst[e], s = src[e];
        if ((unsigned)d >= (unsigned)n || (unsigned)s >= (unsigned)n) return;
        atomicAdd(&g_cnt[d], 1);
        g_link[e] = atomicExch(&g_head[4 * d + (e & 3)], e);
    }
}

// ---------------------------------------------------------------------------
// xs = S @ x: warp per node walking 4 chains simultaneously (spine MLP=4).
// lane = 4 cols (float4). dinv inline from cnt. Split bf16 output.
// ---------------------------------------------------------------------------
__global__ __launch_bounds__(256)
void agg_warp_kernel(const float* __restrict__ x, const int* __restrict__ src,
                     int n) {
    const int node = (blockIdx.x * blockDim.x + threadIdx.x) >> 5;
    if (node >= n) return;
    const int lane = threadIdx.x & 31;
    const float di = rsqrtf(1.0f + (float)g_cnt[node]);
    float4 v = *(const float4*)&x[(size_t)node * DIN + lane * 4];
    float a0 = di * v.x, a1 = di * v.y, a2 = di * v.z, a3 = di * v.w;
    int e0 = g_head[4 * node + 0];
    int e1 = g_head[4 * node + 1];
    int e2 = g_head[4 * node + 2];
    int e3 = g_head[4 * node + 3];
    while ((e0 >= 0) | (e1 >= 0) | (e2 >= 0) | (e3 >= 0)) {
        int s0 = -1, s1 = -1, s2 = -1, s3 = -1;
        int n0 = -1, n1 = -1, n2 = -1, n3 = -1;
        if (e0 >= 0) { s0 = src[e0]; n0 = g_link[e0]; }
        if (e1 >= 0) { s1 = src[e1]; n1 = g_link[e1]; }
        if (e2 >= 0) { s2 = src[e2]; n2 = g_link[e2]; }
        if (e3 >= 0) { s3 = src[e3]; n3 = g_link[e3]; }
        if (s0 >= 0) {
            const float ds = rsqrtf(1.0f + (float)g_cnt[s0]);
            const float4 u = *(const float4*)&x[(size_t)s0 * DIN + lane * 4];
            a0 += ds * u.x; a1 += ds * u.y; a2 += ds * u.z; a3 += ds * u.w;
        }
        if (s1 >= 0) {
            const float ds = rsqrtf(1.0f + (float)g_cnt[s1]);
            const float4 u = *(const float4*)&x[(size_t)s1 * DIN + lane * 4];
            a0 += ds * u.x; a1 += ds * u.y; a2 += ds * u.z; a3 += ds * u.w;
        }
        if (s2 >= 0) {
            const float ds = rsqrtf(1.0f + (float)g_cnt[s2]);
            const float4 u = *(const float4*)&x[(size_t)s2 * DIN + lane * 4];
            a0 += ds * u.x; a1 += ds * u.y; a2 += ds * u.z; a3 += ds * u.w;
        }
        if (s3 >= 0) {
            const float ds = rsqrtf(1.0f + (float)g_cnt[s3]);
            const float4 u = *(const float4*)&x[(size_t)s3 * DIN + lane * 4];
            a0 += ds * u.x; a1 += ds * u.y; a2 += ds * u.z; a3 += ds * u.w;
        }
        e0 = n0; e1 = n1; e2 = n2; e3 = n3;
    }
    a0 *= di; a1 *= di; a2 *= di; a3 *= di;
    const size_t idx = (size_t)node * DIN + lane * 4;
    const __nv_bfloat162 h01 = __floats2bfloat162_rn(a0, a1);
    const __nv_bfloat162 h23 = __floats2bfloat162_rn(a2, a3);
    *(__nv_bfloat162*)&g_xs_h[idx] = h01;
    *(__nv_bfloat162*)&g_xs_h[idx + 2] = h23;
    *(__nv_bfloat162*)&g_xs_l[idx] = __floats2bfloat162_rn(
        a0 - __bfloat162float(h01.x), a1 - __bfloat162float(h01.y));
    *(__nv_bfloat162*)&g_xs_l[idx + 2] = __floats2bfloat162_rn(
        a2 - __bfloat162float(h23.x), a3 - __bfloat162float(h23.y));
}

// ---------------------------------------------------------------------------
// Launch
// ---------------------------------------------------------------------------
extern "C" void kernel_launch(void* const* d_in, const int* in_sizes, int n_in,
                              void* d_out, int out_size) {
    const float* x     = (const float*)d_in[0];
    const int*   ei    = (const int*)d_in[1];
    const float* W_gcn = (const float*)d_in[2];
    const float* b_gcn = (const float*)d_in[3];
    const float* W1    = (const float*)d_in[4];
    const float* b1    = (const float*)d_in[5];
    const float* W2    = (const float*)d_in[6];
    const float* b2    = (const float*)d_in[7];
    const float* W3    = (const float*)d_in[8];
    const float* b3    = (const float*)d_in[9];
    const float* Wout  = (const float*)d_in[10];
    const float* bout  = (const float*)d_in[11];
    float* out = (float*)d_out;

    const int N = in_sizes[0] / DIN;
    const int E = in_sizes[1] / 2;
    const int* src = ei;
    const int* dst = ei + E;

    bf16 *p_xs_h, *p_xs_l, *p_h1_h, *p_h1_l, *p_h2_h, *p_h2_l;
    bf16 *p_Wc_h, *p_Wc_l, *p_W2_h, *p_W2_l, *p_W3_h, *p_W3_l;
    float* p_bc;
    cudaGetSymbolAddress((void**)&p_xs_h, g_xs_h);
    cudaGetSymbolAddress((void**)&p_xs_l, g_xs_l);
    cudaGetSymbolAddress((void**)&p_h1_h, g_h1_h);
    cudaGetSymbolAddress((void**)&p_h1_l, g_h1_l);
    cudaGetSymbolAddress((void**)&p_h2_h, g_h2_h);
    cudaGetSymbolAddress((void**)&p_h2_l, g_h2_l);
    cudaGetSymbolAddress((void**)&p_Wc_h, g_Wc_h);
    cudaGetSymbolAddress((void**)&p_Wc_l, g_Wc_l);
    cudaGetSymbolAddress((void**)&p_W2_h, g_W2_h);
    cudaGetSymbolAddress((void**)&p_W2_l, g_W2_l);
    cudaGetSymbolAddress((void**)&p_W3_h, g_W3_h);
    cudaGetSymbolAddress((void**)&p_W3_l, g_W3_l);
    cudaGetSymbolAddress((void**)&p_bc, g_bc);

    const int SMEM = 98304;  // 3 stages x 32KB
    cudaFuncSetAttribute(mma_gemm<128, true, false>,
                         cudaFuncAttributeMaxDynamicSharedMemorySize, SMEM);
    cudaFuncSetAttribute(mma_gemm<256, true, false>,
                         cudaFuncAttributeMaxDynamicSharedMemorySize, SMEM);
    cudaFuncSetAttribute(mma_gemm<256, true, true>,
                         cudaFuncAttributeMaxDynamicSharedMemorySize, SMEM);

    // 1) prep: W2/W3 split + out=b_out + heads=-1 + cnt=0
    prep_all<<<DIV_UP(PW1 + N, 256), 256>>>(W2, W3, bout, out, N);
    // 2) Wc = W_gcn@W1 (+bc)
    wc_bc_kernel<<<DIN + 1, 256>>>(W_gcn, W1, b_gcn, b1);
    // 3) 4-chain bucket lists + degree counts
    scatter_ll<<<DIV_UP(E, 256), 256>>>(src, dst, E, N);
    // 4) xs = S @ x  (split bf16 output), warp per node
    agg_warp_kernel<<<DIV_UP(N * 32, 256), 256>>>(x, src, N);

    const int mt = DIV_UP(N, 128);
    const dim3 grid(HDIM / 128, mt);
    // 5) h1 = leaky(xs @ Wc + bc)
    mma_gemm<128, true, false><<<grid, 256, SMEM>>>(
        p_xs_h, p_xs_l, p_Wc_h, p_Wc_l, p_bc, p_h1_h, p_h1_l,
        nullptr, nullptr, HDIM, N);
    // 6) h2 = leaky(h1 @ W2 + b2)   <- profiled by ncu (-s 5 -c 1)
    mma_gemm<256, true, false><<<grid, 256, SMEM>>>(
        p_h1_h, p_h1_l, p_W2_h, p_W2_l, b2, p_h2_h, p_h2_l,
        nullptr, nullptr, HDIM, N);
    // 7) out += leaky(h2 @ W3 + b3) . Wout   (fused)
    mma_gemm<256, true, true><<<grid, 256, SMEM>>>(
        p_h2_h, p_h2_l, p_W3_h, p_W3_l, b3, nullptr, nullptr,
        Wout, out, HDIM, N);
}

// round 15
// speedup vs baseline: 1.0285x; 1.0285x over previous
#include <cuda_runtime.h>
#include <cuda_bf16.h>
#include <stdint.h>

// ---------------------------------------------------------------------------
// N=50000, D=128, GCN out=512, H=256, E=800000. edge_index int32.
// h1 = leaky(xs @ (W_gcn@W1) + (b_gcn@W1 + b1)),  xs = S @ x.
// Graph agg: 4-chain linked lists; xn = dinv*x precomputed so the edge loop
// is pure row-sum (FADD), no per-edge normalization instructions.
// 3 GEMMs (K=128,256,256), mma.sync bf16x3 split, W_out dot fused in GEMM3.
// ---------------------------------------------------------------------------
#define MAXN  50000
#define MAXNP 50048      // multiple of 128; padded rows are zero
#define MAXE  800000
#define DIN   128
#define DGCN  512
#define HDIM  256
#define DIV_UP(a, b) (((a) + (b) - 1) / (b))

typedef __nv_bfloat16 bf16;

// ---- scratch (device globals; zero-initialized at module load) ----
__device__ bf16  g_xs_h[(size_t)MAXNP * DIN],  g_xs_l[(size_t)MAXNP * DIN];
__device__ bf16  g_h1_h[(size_t)MAXNP * HDIM], g_h1_l[(size_t)MAXNP * HDIM];
__device__ bf16  g_h2_h[(size_t)MAXNP * HDIM], g_h2_l[(size_t)MAXNP * HDIM];
__device__ float g_xn[(size_t)MAXN * DIN];     // dinv[i] * x[i]
// combined + split weights [NOUT, K]
__device__ bf16  g_Wc_h[HDIM * DIN],  g_Wc_l[HDIM * DIN];   // (W_gcn@W1)^T split
__device__ float g_bc[HDIM];                                 // b_gcn@W1 + b1
__device__ bf16  g_W2_h[HDIM * HDIM], g_W2_l[HDIM * HDIM];
__device__ bf16  g_W3_h[HDIM * HDIM], g_W3_l[HDIM * HDIM];
// graph: 4 interleaved chains per node
__device__ int g_head[4 * MAXN], g_cnt[MAXN], g_link[MAXE];

__device__ __forceinline__ float leaky(float v) { return v > 0.f ? v : 0.1f * v; }

__device__ __forceinline__ uint32_t smem_u32(const void* p) {
    uint32_t a;
    asm("{ .reg .u64 t; cvta.to.shared.u64 t, %1; cvt.u32.u64 %0, t; }"
        : "=r"(a) : "l"(p));
    return a;
}

// smem tile: 128 rows x 64 bytes (32 bf16); chunk = 16B; swizzle keeps
// ldmatrix 8-lane phases and cp.async writes conflict-free.
__device__ __forceinline__ uint32_t swz(int row, int chunk) {
    return (uint32_t)(row * 64 + ((chunk ^ ((row ^ (row >> 2)) & 3)) * 16));
}

#define LDSM4(r, addr)                                                         \
    asm volatile("ldmatrix.sync.aligned.m8n8.x4.shared.b16 {%0,%1,%2,%3}, [%4];" \
                 : "=r"((r)[0]), "=r"((r)[1]), "=r"((r)[2]), "=r"((r)[3])      \
                 : "r"(addr))

#define MMA16(c, av, b0, b1)                                                   \
    asm volatile("mma.sync.aligned.m16n8k16.row.col.f32.bf16.bf16.f32 "        \
                 "{%0,%1,%2,%3}, {%4,%5,%6,%7}, {%8,%9}, {%0,%1,%2,%3};"       \
                 : "+f"((c)[0]), "+f"((c)[1]), "+f"((c)[2]), "+f"((c)[3])      \
                 : "r"((av)[0]), "r"((av)[1]), "r"((av)[2]), "r"((av)[3]),     \
                   "r"(b0), "r"(b1))

// ---------------------------------------------------------------------------
// bf16x3 warp-MMA GEMM: C[M,NOUT] = split(A[M,K]) @ split(B[NOUT,K])^T
// Block 128x128, BK=32, 256 thr (8 warps, 2x4), warp tile 64x32.
// DOTOUT: fuse out[r] += sum_col leaky(C[r,col]+bias[col]) * wout[col].
// ---------------------------------------------------------------------------
template <int K, bool LEAKY, bool DOTOUT>
__global__ __launch_bounds__(256, 2)
void mma_gemm(const bf16* __restrict__ Ah, const bf16* __restrict__ Al,
              const bf16* __restrict__ Bh, const bf16* __restrict__ Bl,
              const float* __restrict__ bias,
              bf16* __restrict__ Ch, bf16* __restrict__ Cl,
              const float* __restrict__ wout, float* __restrict__ dout,
              int NOUT, int MREAL) {
    extern __shared__ char sm[];
    const uint32_t sbase = smem_u32(sm);

    const int tid = threadIdx.x;
    const int lane = tid & 31, wid = tid >> 5;
    const int wm = wid >> 2, wn = wid & 3;        // 2 x 4 warp grid
    const int brow = blockIdx.y * 128;
    const int bcol = blockIdx.x * 128;

    float acc[4][4][4] = {};
    constexpr int NST = K / 32;

    // per-thread cp.async slots (2 chunks x 4 tiles), hoisted
    const int idx0 = tid * 2;                     // 0..510 within tile
    const int row0 = idx0 >> 2, c0 = idx0 & 3;
    const int row1 = (idx0 + 1) >> 2, c1 = (idx0 + 1) & 3;
    const uint32_t so0 = swz(row0, c0), so1 = swz(row1, c1);

    auto load_stage = [&](int s, int buf) {
        const int kofs = s * 32;
        const uint32_t sb = sbase + buf * 32768;
        const bf16* srcs[4] = {
            Ah + (size_t)brow * K + kofs, Al + (size_t)brow * K + kofs,
            Bh + (size_t)bcol * K + kofs, Bl + (size_t)bcol * K + kofs};
#pragma unroll
        for (int tile = 0; tile < 4; ++tile) {
            const bf16* base = srcs[tile];
            const uint32_t d = sb + tile * 8192;
            asm volatile("cp.async.cg.shared.global [%0], [%1], 16;"
                         :: "r"(d + so0), "l"(base + (size_t)row0 * K + c0 * 8));
            asm volatile("cp.async.cg.shared.global [%0], [%1], 16;"
                         :: "r"(d + so1), "l"(base + (size_t)row1 * K + c1 * 8));
        }
        asm volatile("cp.async.commit_group;" ::: "memory");
    };

    // ldmatrix address pieces (constant per thread across stages)
    const int arow_base = wm * 64 + (lane & 7) + ((lane >> 3) & 1) * 8;
    const int ach_half = lane >> 4;                       // 0/1
    const int brow_base = wn * 32 + ((lane >> 4) & 1) * 8 + (lane & 7);
    const int bch_half = (lane >> 3) & 1;                 // 0/1

    auto do_compute = [&](int buf) {
        const uint32_t sb = sbase + buf * 32768;
        const uint32_t Ahb = sb, Alb = sb + 8192;
        const uint32_t Bhb = sb + 16384, Blb = sb + 24576;
#pragma unroll
        for (int ks = 0; ks < 2; ++ks) {
            const int ach = ks * 2 + ach_half;
            const int bch = ks * 2 + bch_half;
            uint32_t a[4][4], bh[4][2], bl[4][2];
#pragma unroll
            for (int mi = 0; mi < 4; ++mi)
                LDSM4(a[mi], Ahb + swz(arow_base + mi * 16, ach));
#pragma unroll
            for (int p = 0; p < 2; ++p) {
                uint32_t r[4];
                LDSM4(r, Bhb + swz(brow_base + p * 16, bch));
                bh[p * 2][0] = r[0]; bh[p * 2][1] = r[1];
                bh[p * 2 + 1][0] = r[2]; bh[p * 2 + 1][1] = r[3];
            }
            // t0: Ah x Bh
#pragma unroll
            for (int mi = 0; mi < 4; ++mi)
#pragma unroll
                for (int ni = 0; ni < 4; ++ni)
                    MMA16(acc[mi][ni], a[mi], bh[ni][0], bh[ni][1]);
#pragma unroll
            for (int p = 0; p < 2; ++p) {
                uint32_t r[4];
                LDSM4(r, Blb + swz(brow_base + p * 16, bch));
                bl[p * 2][0] = r[0]; bl[p * 2][1] = r[1];
                bl[p * 2 + 1][0] = r[2]; bl[p * 2 + 1][1] = r[3];
            }
            // t1: Ah x Bl  (reuse a)
#pragma unroll
            for (int mi = 0; mi < 4; ++mi)
#pragma unroll
                for (int ni = 0; ni < 4; ++ni)
                    MMA16(acc[mi][ni], a[mi], bl[ni][0], bl[ni][1]);
            // Al fragments (overwrite a)
#pragma unroll
            for (int mi = 0; mi < 4; ++mi)
                LDSM4(a[mi], Alb + swz(arow_base + mi * 16, ach));
            // t2: Al x Bh  (reuse bh)
#pragma unroll
            for (int mi = 0; mi < 4; ++mi)
#pragma unroll
                for (int ni = 0; ni < 4; ++ni)
                    MMA16(acc[mi][ni], a[mi], bh[ni][0], bh[ni][1]);
        }
    };

    // 3-stage circular pipeline, loads run 2 stages ahead
    load_stage(0, 0);
    if (NST > 1) load_stage(1, 1);
    for (int s = 0; s < NST; ++s) {
        if (s + 1 < NST)
            asm volatile("cp.async.wait_group 1;" ::: "memory");
        else
            asm volatile("cp.async.wait_group 0;" ::: "memory");
        __syncthreads();
        if (s + 2 < NST) load_stage(s + 2, (s + 2) % 3);
        do_compute(s % 3);
    }

    // ---- epilogue ----
    if (DOTOUT) {
        float rs[4][2] = {};   // per (mi, h) partial row dots
#pragma unroll
        for (int mi = 0; mi < 4; ++mi) {
#pragma unroll
            for (int ni = 0; ni < 4; ++ni) {
                const int col = bcol + wn * 32 + ni * 8 + (lane & 3) * 2;
                const float2 bb = *(const float2*)&bias[col];
                const float2 wo = *(const float2*)&wout[col];
#pragma unroll
                for (int h = 0; h < 2; ++h) {
                    float v0 = acc[mi][ni][h * 2 + 0] + bb.x;
                    float v1 = acc[mi][ni][h * 2 + 1] + bb.y;
                    if (LEAKY) { v0 = leaky(v0); v1 = leaky(v1); }
                    rs[mi][h] += v0 * wo.x + v1 * wo.y;
                }
            }
        }
#pragma unroll
        for (int mi = 0; mi < 4; ++mi)
#pragma unroll
            for (int h = 0; h < 2; ++h) {
                rs[mi][h] += __shfl_xor_sync(0xFFFFFFFFu, rs[mi][h], 1);
                rs[mi][h] += __shfl_xor_sync(0xFFFFFFFFu, rs[mi][h], 2);
            }
        if ((lane & 3) == 0) {
            const int rbase = brow + wm * 64 + (lane >> 2);
#pragma unroll
            for (int mi = 0; mi < 4; ++mi)
#pragma unroll
                for (int h = 0; h < 2; ++h) {
                    const int r = rbase + mi * 16 + h * 8;
                    if (r < MREAL) atomicAdd(&dout[r], rs[mi][h]);
                }
        }
    } else {
#pragma unroll
        for (int mi = 0; mi < 4; ++mi) {
            const int r0 = brow + wm * 64 + mi * 16 + (lane >> 2);
#pragma unroll
            for (int ni = 0; ni < 4; ++ni) {
                const int col = bcol + wn * 32 + ni * 8 + (lane & 3) * 2;
                const float2 bb = *(const float2*)&bias[col];
#pragma unroll
                for (int h = 0; h < 2; ++h) {
                    const int r = r0 + h * 8;
                    float v0 = acc[mi][ni][h * 2 + 0] + bb.x;
                    float v1 = acc[mi][ni][h * 2 + 1] + bb.y;
                    if (LEAKY) { v0 = leaky(v0); v1 = leaky(v1); }
                    const __nv_bfloat162 hv = __floats2bfloat162_rn(v0, v1);
                    *(__nv_bfloat162*)&Ch[(size_t)r * NOUT + col] = hv;
                    const float l0 = v0 - __bfloat162float(hv.x);
                    const float l1 = v1 - __bfloat162float(hv.y);
                    *(__nv_bfloat162*)&Cl[(size_t)r * NOUT + col] =
                        __floats2bfloat162_rn(l0, l1);
                }
            }
        }
    }
}

// ---------------------------------------------------------------------------
// Fused prep: blocks 0..127 = Wc rows, block 128 = bc, blocks >128 =
// W2/W3 transpose+split + out=b_out + heads=-1 + cnt=0.
// ---------------------------------------------------------------------------
#define PW0 (HDIM * HDIM)
#define PW1 (2 * HDIM * HDIM)
__global__ __launch_bounds__(256)
void prep_fused(const float* __restrict__ Wg, const float* __restrict__ W1,
                const float* __restrict__ bg, const float* __restrict__ b1,
                const float* __restrict__ W2, const float* __restrict__ W3,
                const float* __restrict__ bout, float* __restrict__ out,
                int n) {
    const int b = blockIdx.x;
    const int t = threadIdx.x;
    if (b < DIN) {                      // Wc row
        __shared__ float row[DGCN];
        row[t] = Wg[(size_t)b * DGCN + t];
        row[t + 256] = Wg[(size_t)b * DGCN + t + 256];
        __syncthreads();
        float acc = 0.f;
#pragma unroll 8
        for (int j = 0; j < DGCN; ++j)
            acc += row[j] * W1[(size_t)j * HDIM + t];
        const bf16 h = __float2bfloat16(acc);
        g_Wc_h[t * DIN + b] = h;
        g_Wc_l[t * DIN + b] = __float2bfloat16(acc - __bfloat162float(h));
        return;
    }
    if (b == DIN) {                     // bc
        float acc = b1[t];
#pragma unroll 8
        for (int j = 0; j < DGCN; ++j)
            acc += bg[j] * W1[(size_t)j * HDIM + t];
        g_bc[t] = acc;
        return;
    }
    const int g = (b - DIN - 1) * 256 + t;
    if (g >= PW1) {
        const int i = g - PW1;
        if (i < n) {
            out[i] = bout[0];
            g_cnt[i] = 0;
            g_head[4 * i + 0] = -1;
            g_head[4 * i + 1] = -1;
            g_head[4 * i + 2] = -1;
            g_head[4 * i + 3] = -1;
        }
        return;
    }
    const float* W; bf16 *Th, *Tl; int idx;
    if (g < PW0) { W = W2; Th = g_W2_h; Tl = g_W2_l; idx = g; }
    else         { W = W3; Th = g_W3_h; Tl = g_W3_l; idx = g - PW0; }
    const int n2 = idx / HDIM, k = idx % HDIM;
    const float v = W[(size_t)k * HDIM + n2];
    const bf16 h = __float2bfloat16(v);
    Th[idx] = h;
    Tl[idx] = __float2bfloat16(v - __bfloat162float(h));
}

// ---------------------------------------------------------------------------
// 4-chain bucket scatter: chain (d, e&3); cnt[dst]++.
// ---------------------------------------------------------------------------
__global__ void scatter_ll(const int* __restrict__ src,
                           const int* __restrict__ dst, int E, int n) {
    int e = blockIdx.x * blockDim.x + threadIdx.x;
    if (e < E) {
        int d = dst[e], s = src[e];
        if ((unsigned)d >= (unsigned)n || (unsigned)s >= (unsigned)n) return;
        atomicAdd(&g_cnt[d], 1);
        g_link[e] = atomicExch(&g_head[4 * d + (e & 3)], e);
    }
}

// ---------------------------------------------------------------------------
// xn[i] = dinv[i] * x[i]   (warp per node; one rsqrt per warp)
// ---------------------------------------------------------------------------
__global__ __launch_bounds__(256)
void xn_kernel(const float* __restrict__ x, int n) {
    const int node = (blockIdx.x * blockDim.x + threadIdx.x) >> 5;
    if (node >= n) return;
    const int lane = threadIdx.x & 31;
    const float di = rsqrtf(1.0f + (float)g_cnt[node]);
    const size_t idx = (size_t)node * DIN + lane * 4;
    float4 v = *(const float4*)&x[idx];
    v.x *= di; v.y *= di; v.z *= di; v.w *= di;
    *(float4*)&g_xn[idx] = v;
}

// ---------------------------------------------------------------------------
// xs = S @ x: warp per node, 4 chains, pure xn-row sums (FADD only).
// ---------------------------------------------------------------------------
__global__ __launch_bounds__(256)
void agg_warp_kernel(const int* __restrict__ src, int n) {
    const int node = (blockIdx.x * blockDim.x + threadIdx.x) >> 5;
    if (node >= n) return;
    const int lane = threadIdx.x & 31;
    const size_t nidx = (size_t)node * DIN + lane * 4;
    float4 v = *(const float4*)&g_xn[nidx];     // self term dinv*x[node]
    float a0 = v.x, a1 = v.y, a2 = v.z, a3 = v.w;
    int e0 = g_head[4 * node + 0];
    int e1 = g_head[4 * node + 1];
    int e2 = g_head[4 * node + 2];
    int e3 = g_head[4 * node + 3];
    while ((e0 >= 0) | (e1 >= 0) | (e2 >= 0) | (e3 >= 0)) {
        int s0 = -1, s1 = -1, s2 = -1, s3 = -1;
        int n0 = -1, n1 = -1, n2 = -1, n3 = -1;
        if (e0 >= 0) { s0 = src[e0]; n0 = g_link[e0]; }
        if (e1 >= 0) { s1 = src[e1]; n1 = g_link[e1]; }
        if (e2 >= 0) { s2 = src[e2]; n2 = g_link[e2]; }
        if (e3 >= 0) { s3 = src[e3]; n3 = g_link[e3]; }
        if (s0 >= 0) {
            const float4 u = *(const float4*)&g_xn[(size_t)s0 * DIN + lane * 4];
            a0 += u.x; a1 += u.y; a2 += u.z; a3 += u.w;
        }
        if (s1 >= 0) {
            const float4 u = *(const float4*)&g_xn[(size_t)s1 * DIN + lane * 4];
            a0 += u.x; a1 += u.y; a2 += u.z; a3 += u.w;
        }
        if (s2 >= 0) {
            const float4 u = *(const float4*)&g_xn[(size_t)s2 * DIN + lane * 4];
            a0 += u.x; a1 += u.y; a2 += u.z; a3 += u.w;
        }
        if (s3 >= 0) {
            const float4 u = *(const float4*)&g_xn[(size_t)s3 * DIN + lane * 4];
            a0 += u.x; a1 += u.y; a2 += u.z; a3 += u.w;
        }
        e0 = n0; e1 = n1; e2 = n2; e3 = n3;
    }
    const float di = rsqrtf(1.0f + (float)g_cnt[node]);
    a0 *= di; a1 *= di; a2 *= di; a3 *= di;
    const __nv_bfloat162 h01 = __floats2bfloat162_rn(a0, a1);
    const __nv_bfloat162 h23 = __floats2bfloat162_rn(a2, a3);
    *(__nv_bfloat162*)&g_xs_h[nidx] = h01;
    *(__nv_bfloat162*)&g_xs_h[nidx + 2] = h23;
    *(__nv_bfloat162*)&g_xs_l[nidx] = __floats2bfloat162_rn(
        a0 - __bfloat162float(h01.x), a1 - __bfloat162float(h01.y));
    *(__nv_bfloat162*)&g_xs_l[nidx + 2] = __floats2bfloat162_rn(
        a2 - __bfloat162float(h23.x), a3 - __bfloat162float(h23.y));
}

// ---------------------------------------------------------------------------
// Launch
// ---------------------------------------------------------------------------
extern "C" void kernel_launch(void* const* d_in, const int* in_sizes, int n_in,
                              void* d_out, int out_size) {
    const float* x     = (const float*)d_in[0];
    const int*   ei    = (const int*)d_in[1];
    const float* W_gcn = (const float*)d_in[2];
    const float* b_gcn = (const float*)d_in[3];
    const float* W1    = (const float*)d_in[4];
    const float* b1    = (const float*)d_in[5];
    const float* W2    = (const float*)d_in[6];
    const float* b2    = (const float*)d_in[7];
    const float* W3    = (const float*)d_in[8];
    const float* b3    = (const float*)d_in[9];
    const float* Wout  = (const float*)d_in[10];
    const float* bout  = (const float*)d_in[11];
    float* out = (float*)d_out;

    const int N = in_sizes[0] / DIN;
    const int E = in_sizes[1] / 2;
    const int* src = ei;
    const int* dst = ei + E;

    bf16 *p_xs_h, *p_xs_l, *p_h1_h, *p_h1_l, *p_h2_h, *p_h2_l;
    bf16 *p_Wc_h, *p_Wc_l, *p_W2_h, *p_W2_l, *p_W3_h, *p_W3_l;
    float* p_bc;
    cudaGetSymbolAddress((void**)&p_xs_h, g_xs_h);
    cudaGetSymbolAddress((void**)&p_xs_l, g_xs_l);
    cudaGetSymbolAddress((void**)&p_h1_h, g_h1_h);
    cudaGetSymbolAddress((void**)&p_h1_l, g_h1_l);
    cudaGetSymbolAddress((void**)&p_h2_h, g_h2_h);
    cudaGetSymbolAddress((void**)&p_h2_l, g_h2_l);
    cudaGetSymbolAddress((void**)&p_Wc_h, g_Wc_h);
    cudaGetSymbolAddress((void**)&p_Wc_l, g_Wc_l);
    cudaGetSymbolAddress((void**)&p_W2_h, g_W2_h);
    cudaGetSymbolAddress((void**)&p_W2_l, g_W2_l);
    cudaGetSymbolAddress((void**)&p_W3_h, g_W3_h);
    cudaGetSymbolAddress((void**)&p_W3_l, g_W3_l);
    cudaGetSymbolAddress((void**)&p_bc, g_bc);

    const int SMEM = 98304;  // 3 stages x 32KB
    cudaFuncSetAttribute(mma_gemm<128, true, false>,
                         cudaFuncAttributeMaxDynamicSharedMemorySize, SMEM);
    cudaFuncSetAttribute(mma_gemm<256, true, false>,
                         cudaFuncAttributeMaxDynamicSharedMemorySize, SMEM);
    cudaFuncSetAttribute(mma_gemm<256, true, true>,
                         cudaFuncAttributeMaxDynamicSharedMemorySize, SMEM);

    // 1) fused prep: Wc/bc + W2/W3 split + out=b_out + heads/cnt init
    prep_fused<<<DIN + 1 + DIV_UP(PW1 + N, 256), 256>>>(
        W_gcn, W1, b_gcn, b1, W2, W3, bout, out, N);
    // 2) 4-chain bucket lists + degree counts
    scatter_ll<<<DIV_UP(E, 256), 256>>>(src, dst, E, N);
    // 3) xn = dinv * x
    xn_kernel<<<DIV_UP(N * 32, 256), 256>>>(x, N);
    // 4) xs = S @ x  (split bf16 output), warp per node
    agg_warp_kernel<<<DIV_UP(N * 32, 256), 256>>>(src, N);

    const int mt = DIV_UP(N, 128);
    const dim3 grid(HDIM / 128, mt);
    // 5) h1 = leaky(xs @ Wc + bc)
    mma_gemm<128, true, false><<<grid, 256, SMEM>>>(
        p_xs_h, p_xs_l, p_Wc_h, p_Wc_l, p_bc, p_h1_h, p_h1_l,
        nullptr, nullptr, HDIM, N);
    // 6) h2 = leaky(h1 @ W2 + b2)
    mma_gemm<256, true, false><<<grid, 256, SMEM>>>(
        p_h1_h, p_h1_l, p_W2_h, p_W2_l, b2, p_h2_h, p_h2_l,
        nullptr, nullptr, HDIM, N);
    // 7) out += leaky(h2 @ W3 + b3) . Wout   (fused)
    mma_gemm<256, true, true><<<grid, 256, SMEM>>>(
        p_h2_h, p_h2_l, p_W3_h, p_W3_l, b3, nullptr, nullptr,
        Wout, out, HDIM, N);
}

// round 16
// speedup vs baseline: 1.0420x; 1.0132x over previous
#include <cuda_runtime.h>
#include <cuda_bf16.h>
#include <stdint.h>

// ---------------------------------------------------------------------------
// N=50000, D=128, GCN out=512, H=256, E=800000. edge_index int32.
// h1 = leaky(xs @ (W_gcn@W1) + (b_gcn@W1 + b1)),  xs = S @ x.
// Graph agg: 4-chain lists with PACKED int2 {src,link} edge records;
// xn = dinv*x precomputed -> edge loop is one LDG.64 + one row LDG + FADDs.
// 3 GEMMs (K=128,256,256), mma.sync bf16x3 split, W_out dot fused in GEMM3.
// ---------------------------------------------------------------------------
#define MAXN  50000
#define MAXNP 50048      // multiple of 128; padded rows are zero
#define MAXE  800000
#define DIN   128
#define DGCN  512
#define HDIM  256
#define DIV_UP(a, b) (((a) + (b) - 1) / (b))

typedef __nv_bfloat16 bf16;

// ---- scratch (device globals; zero-initialized at module load) ----
__device__ bf16  g_xs_h[(size_t)MAXNP * DIN],  g_xs_l[(size_t)MAXNP * DIN];
__device__ bf16  g_h1_h[(size_t)MAXNP * HDIM], g_h1_l[(size_t)MAXNP * HDIM];
__device__ bf16  g_h2_h[(size_t)MAXNP * HDIM], g_h2_l[(size_t)MAXNP * HDIM];
__device__ float g_xn[(size_t)MAXN * DIN];     // dinv[i] * x[i]
// combined + split weights [NOUT, K]
__device__ bf16  g_Wc_h[HDIM * DIN],  g_Wc_l[HDIM * DIN];   // (W_gcn@W1)^T split
__device__ float g_bc[HDIM];                                 // b_gcn@W1 + b1
__device__ bf16  g_W2_h[HDIM * HDIM], g_W2_l[HDIM * HDIM];
__device__ bf16  g_W3_h[HDIM * HDIM], g_W3_l[HDIM * HDIM];
// graph: 4 interleaved chains per node; packed edge record {src, next}
__device__ int  g_head[4 * MAXN], g_cnt[MAXN];
__device__ int2 g_edge[MAXE];

__device__ __forceinline__ float leaky(float v) { return v > 0.f ? v : 0.1f * v; }

__device__ __forceinline__ uint32_t smem_u32(const void* p) {
    uint32_t a;
    asm("{ .reg .u64 t; cvta.to.shared.u64 t, %1; cvt.u32.u64 %0, t; }"
        : "=r"(a) : "l"(p));
    return a;
}

// smem tile: 128 rows x 64 bytes (32 bf16); chunk = 16B; swizzle keeps
// ldmatrix 8-lane phases and cp.async writes conflict-free.
__device__ __forceinline__ uint32_t swz(int row, int chunk) {
    return (uint32_t)(row * 64 + ((chunk ^ ((row ^ (row >> 2)) & 3)) * 16));
}

#define LDSM4(r, addr)                                                         \
    asm volatile("ldmatrix.sync.aligned.m8n8.x4.shared.b16 {%0,%1,%2,%3}, [%4];" \
                 : "=r"((r)[0]), "=r"((r)[1]), "=r"((r)[2]), "=r"((r)[3])      \
                 : "r"(addr))

#define MMA16(c, av, b0, b1)                                                   \
    asm volatile("mma.sync.aligned.m16n8k16.row.col.f32.bf16.bf16.f32 "        \
                 "{%0,%1,%2,%3}, {%4,%5,%6,%7}, {%8,%9}, {%0,%1,%2,%3};"       \
                 : "+f"((c)[0]), "+f"((c)[1]), "+f"((c)[2]), "+f"((c)[3])      \
                 : "r"((av)[0]), "r"((av)[1]), "r"((av)[2]), "r"((av)[3]),     \
                   "r"(b0), "r"(b1))

// ---------------------------------------------------------------------------
// bf16x3 warp-MMA GEMM: C[M,NOUT] = split(A[M,K]) @ split(B[NOUT,K])^T
// Block 128x128, BK=32, 256 thr (8 warps, 2x4), warp tile 64x32.
// DOTOUT: fuse out[r] += sum_col leaky(C[r,col]+bias[col]) * wout[col].
// ---------------------------------------------------------------------------
template <int K, bool LEAKY, bool DOTOUT>
__global__ __launch_bounds__(256, 2)
void mma_gemm(const bf16* __restrict__ Ah, const bf16* __restrict__ Al,
              const bf16* __restrict__ Bh, const bf16* __restrict__ Bl,
              const float* __restrict__ bias,
              bf16* __restrict__ Ch, bf16* __restrict__ Cl,
              const float* __restrict__ wout, float* __restrict__ dout,
              int NOUT, int MREAL) {
    extern __shared__ char sm[];
    const uint32_t sbase = smem_u32(sm);

    const int tid = threadIdx.x;
    const int lane = tid & 31, wid = tid >> 5;
    const int wm = wid >> 2, wn = wid & 3;        // 2 x 4 warp grid
    const int brow = blockIdx.y * 128;
    const int bcol = blockIdx.x * 128;

    float acc[4][4][4] = {};
    constexpr int NST = K / 32;

    // per-thread cp.async slots (2 chunks x 4 tiles), hoisted
    const int idx0 = tid * 2;                     // 0..510 within tile
    const int row0 = idx0 >> 2, c0 = idx0 & 3;
    const int row1 = (idx0 + 1) >> 2, c1 = (idx0 + 1) & 3;
    const uint32_t so0 = swz(row0, c0), so1 = swz(row1, c1);

    auto load_stage = [&](int s, int buf) {
        const int kofs = s * 32;
        const uint32_t sb = sbase + buf * 32768;
        const bf16* srcs[4] = {
            Ah + (size_t)brow * K + kofs, Al + (size_t)brow * K + kofs,
            Bh + (size_t)bcol * K + kofs, Bl + (size_t)bcol * K + kofs};
#pragma unroll
        for (int tile = 0; tile < 4; ++tile) {
            const bf16* base = srcs[tile];
            const uint32_t d = sb + tile * 8192;
            asm volatile("cp.async.cg.shared.global [%0], [%1], 16;"
                         :: "r"(d + so0), "l"(base + (size_t)row0 * K + c0 * 8));
            asm volatile("cp.async.cg.shared.global [%0], [%1], 16;"
                         :: "r"(d + so1), "l"(base + (size_t)row1 * K + c1 * 8));
        }
        asm volatile("cp.async.commit_group;" ::: "memory");
    };

    // ldmatrix address pieces (constant per thread across stages)
    const int arow_base = wm * 64 + (lane & 7) + ((lane >> 3) & 1) * 8;
    const int ach_half = lane >> 4;                       // 0/1
    const int brow_base = wn * 32 + ((lane >> 4) & 1) * 8 + (lane & 7);
    const int bch_half = (lane >> 3) & 1;                 // 0/1

    auto do_compute = [&](int buf) {
        const uint32_t sb = sbase + buf * 32768;
        const uint32_t Ahb = sb, Alb = sb + 8192;
        const uint32_t Bhb = sb + 16384, Blb = sb + 24576;
#pragma unroll
        for (int ks = 0; ks < 2; ++ks) {
            const int ach = ks * 2 + ach_half;
            const int bch = ks * 2 + bch_half;
            uint32_t a[4][4], bh[4][2], bl[4][2];
#pragma unroll
            for (int mi = 0; mi < 4; ++mi)
                LDSM4(a[mi], Ahb + swz(arow_base + mi * 16, ach));
#pragma unroll
            for (int p = 0; p < 2; ++p) {
                uint32_t r[4];
                LDSM4(r, Bhb + swz(brow_base + p * 16, bch));
                bh[p * 2][0] = r[0]; bh[p * 2][1] = r[1];
                bh[p * 2 + 1][0] = r[2]; bh[p * 2 + 1][1] = r[3];
            }
            // t0: Ah x Bh
#pragma unroll
            for (int mi = 0; mi < 4; ++mi)
#pragma unroll
                for (int ni = 0; ni < 4; ++ni)
                    MMA16(acc[mi][ni], a[mi], bh[ni][0], bh[ni][1]);
#pragma unroll
            for (int p = 0; p < 2; ++p) {
                uint32_t r[4];
                LDSM4(r, Blb + swz(brow_base + p * 16, bch));
                bl[p * 2][0] = r[0]; bl[p * 2][1] = r[1];
                bl[p * 2 + 1][0] = r[2]; bl[p * 2 + 1][1] = r[3];
            }
            // t1: Ah x Bl  (reuse a)
#pragma unroll
            for (int mi = 0; mi < 4; ++mi)
#pragma unroll
                for (int ni = 0; ni < 4; ++ni)
                    MMA16(acc[mi][ni], a[mi], bl[ni][0], bl[ni][1]);
            // Al fragments (overwrite a)
#pragma unroll
            for (int mi = 0; mi < 4; ++mi)
                LDSM4(a[mi], Alb + swz(arow_base + mi * 16, ach));
            // t2: Al x Bh  (reuse bh)
#pragma unroll
            for (int mi = 0; mi < 4; ++mi)
#pragma unroll
                for (int ni = 0; ni < 4; ++ni)
                    MMA16(acc[mi][ni], a[mi], bh[ni][0], bh[ni][1]);
        }
    };

    // 3-stage circular pipeline, loads run 2 stages ahead
    load_stage(0, 0);
    if (NST > 1) load_stage(1, 1);
    for (int s = 0; s < NST; ++s) {
        if (s + 1 < NST)
            asm volatile("cp.async.wait_group 1;" ::: "memory");
        else
            asm volatile("cp.async.wait_group 0;" ::: "memory");
        __syncthreads();
        if (s + 2 < NST) load_stage(s + 2, (s + 2) % 3);
        do_compute(s % 3);
    }

    // ---- epilogue ----
    if (DOTOUT) {
        float rs[4][2] = {};   // per (mi, h) partial row dots
#pragma unroll
        for (int mi = 0; mi < 4; ++mi) {
#pragma unroll
            for (int ni = 0; ni < 4; ++ni) {
                const int col = bcol + wn * 32 + ni * 8 + (lane & 3) * 2;
                const float2 bb = *(const float2*)&bias[col];
                const float2 wo = *(const float2*)&wout[col];
#pragma unroll
                for (int h = 0; h < 2; ++h) {
                    float v0 = acc[mi][ni][h * 2 + 0] + bb.x;
                    float v1 = acc[mi][ni][h * 2 + 1] + bb.y;
                    if (LEAKY) { v0 = leaky(v0); v1 = leaky(v1); }
                    rs[mi][h] += v0 * wo.x + v1 * wo.y;
                }
            }
        }
#pragma unroll
        for (int mi = 0; mi < 4; ++mi)
#pragma unroll
            for (int h = 0; h < 2; ++h) {
                rs[mi][h] += __shfl_xor_sync(0xFFFFFFFFu, rs[mi][h], 1);
                rs[mi][h] += __shfl_xor_sync(0xFFFFFFFFu, rs[mi][h], 2);
            }
        if ((lane & 3) == 0) {
            const int rbase = brow + wm * 64 + (lane >> 2);
#pragma unroll
            for (int mi = 0; mi < 4; ++mi)
#pragma unroll
                for (int h = 0; h < 2; ++h) {
                    const int r = rbase + mi * 16 + h * 8;
                    if (r < MREAL) atomicAdd(&dout[r], rs[mi][h]);
                }
        }
    } else {
#pragma unroll
        for (int mi = 0; mi < 4; ++mi) {
            const int r0 = brow + wm * 64 + mi * 16 + (lane >> 2);
#pragma unroll
            for (int ni = 0; ni < 4; ++ni) {
                const int col = bcol + wn * 32 + ni * 8 + (lane & 3) * 2;
                const float2 bb = *(const float2*)&bias[col];
#pragma unroll
                for (int h = 0; h < 2; ++h) {
                    const int r = r0 + h * 8;
                    float v0 = acc[mi][ni][h * 2 + 0] + bb.x;
                    float v1 = acc[mi][ni][h * 2 + 1] + bb.y;
                    if (LEAKY) { v0 = leaky(v0); v1 = leaky(v1); }
                    const __nv_bfloat162 hv = __floats2bfloat162_rn(v0, v1);
                    *(__nv_bfloat162*)&Ch[(size_t)r * NOUT + col] = hv;
                    const float l0 = v0 - __bfloat162float(hv.x);
                    const float l1 = v1 - __bfloat162float(hv.y);
                    *(__nv_bfloat162*)&Cl[(size_t)r * NOUT + col] =
                        __floats2bfloat162_rn(l0, l1);
                }
            }
        }
    }
}

// ---------------------------------------------------------------------------
// Fused prep: blocks 0..127 = Wc rows, block 128 = bc, blocks >128 =
// W2/W3 transpose+split + out=b_out + heads=-1 + cnt=0.
// ---------------------------------------------------------------------------
#define PW0 (HDIM * HDIM)
#define PW1 (2 * HDIM * HDIM)
__global__ __launch_bounds__(256)
void prep_fused(const float* __restrict__ Wg, const float* __restrict__ W1,
                const float* __restrict__ bg, const float* __restrict__ b1,
                const float* __restrict__ W2, const float* __restrict__ W3,
                const float* __restrict__ bout, float* __restrict__ out,
                int n) {
    const int b = blockIdx.x;
    const int t = threadIdx.x;
    if (b < DIN) {                      // Wc row
        __shared__ float row[DGCN];
        row[t] = Wg[(size_t)b * DGCN + t];
        row[t + 256] = Wg[(size_t)b * DGCN + t + 256];
        __syncthreads();
        float acc = 0.f;
#pragma unroll 8
        for (int j = 0; j < DGCN; ++j)
            acc += row[j] * W1[(size_t)j * HDIM + t];
        const bf16 h = __float2bfloat16(acc);
        g_Wc_h[t * DIN + b] = h;
        g_Wc_l[t * DIN + b] = __float2bfloat16(acc - __bfloat162float(h));
        return;
    }
    if (b == DIN) {                     // bc
        float acc = b1[t];
#pragma unroll 8
        for (int j = 0; j < DGCN; ++j)
            acc += bg[j] * W1[(size_t)j * HDIM + t];
        g_bc[t] = acc;
        return;
    }
    const int g = (b - DIN - 1) * 256 + t;
    if (g >= PW1) {
        const int i = g - PW1;
        if (i < n) {
            out[i] = bout[0];
            g_cnt[i] = 0;
            g_head[4 * i + 0] = -1;
            g_head[4 * i + 1] = -1;
            g_head[4 * i + 2] = -1;
            g_head[4 * i + 3] = -1;
        }
        return;
    }
    const float* W; bf16 *Th, *Tl; int idx;
    if (g < PW0) { W = W2; Th = g_W2_h; Tl = g_W2_l; idx = g; }
    else         { W = W3; Th = g_W3_h; Tl = g_W3_l; idx = g - PW0; }
    const int n2 = idx / HDIM, k = idx % HDIM;
    const float v = W[(size_t)k * HDIM + n2];
    const bf16 h = __float2bfloat16(v);
    Th[idx] = h;
    Tl[idx] = __float2bfloat16(v - __bfloat162float(h));
}

// ---------------------------------------------------------------------------
// 4-chain bucket scatter with packed edge records: edge[e] = {src, next}.
// ---------------------------------------------------------------------------
__global__ void scatter_ll(const int* __restrict__ src,
                           const int* __restrict__ dst, int E, int n) {
    int e = blockIdx.x * blockDim.x + threadIdx.x;
    if (e < E) {
        int d = dst[e], s = src[e];
        if ((unsigned)d >= (unsigned)n || (unsigned)s >= (unsigned)n) return;
        atomicAdd(&g_cnt[d], 1);
        const int nx = atomicExch(&g_head[4 * d + (e & 3)], e);
        g_edge[e] = make_int2(s, nx);
    }
}

// ---------------------------------------------------------------------------
// xn[i] = dinv[i] * x[i]   (warp per node; one rsqrt per warp)
// ---------------------------------------------------------------------------
__global__ __launch_bounds__(256)
void xn_kernel(const float* __restrict__ x, int n) {
    const int node = (blockIdx.x * blockDim.x + threadIdx.x) >> 5;
    if (node >= n) return;
    const int lane = threadIdx.x & 31;
    const float di = rsqrtf(1.0f + (float)g_cnt[node]);
    const size_t idx = (size_t)node * DIN + lane * 4;
    float4 v = *(const float4*)&x[idx];
    v.x *= di; v.y *= di; v.z *= di; v.w *= di;
    *(float4*)&g_xn[idx] = v;
}

// ---------------------------------------------------------------------------
// xs = S @ x: warp per node, 4 chains, packed int2 edge records.
// ---------------------------------------------------------------------------
__global__ __launch_bounds__(256)
void agg_warp_kernel(int n) {
    const int node = (blockIdx.x * blockDim.x + threadIdx.x) >> 5;
    if (node >= n) return;
    const int lane = threadIdx.x & 31;
    const int cnt = g_cnt[node];                 // hoisted for final rsqrt
    const size_t nidx = (size_t)node * DIN + lane * 4;
    float4 v = *(const float4*)&g_xn[nidx];      // self term dinv*x[node]
    float a0 = v.x, a1 = v.y, a2 = v.z, a3 = v.w;
    int e0 = g_head[4 * node + 0];
    int e1 = g_head[4 * node + 1];
    int e2 = g_head[4 * node + 2];
    int e3 = g_head[4 * node + 3];
    while ((e0 >= 0) | (e1 >= 0) | (e2 >= 0) | (e3 >= 0)) {
        int2 p0, p1, p2, p3;
        p0.x = p1.x = p2.x = p3.x = -1;
        p0.y = p1.y = p2.y = p3.y = -1;
        if (e0 >= 0) p0 = g_edge[e0];
        if (e1 >= 0) p1 = g_edge[e1];
        if (e2 >= 0) p2 = g_edge[e2];
        if (e3 >= 0) p3 = g_edge[e3];
        if (p0.x >= 0) {
            const float4 u = *(const float4*)&g_xn[(size_t)p0.x * DIN + lane * 4];
            a0 += u.x; a1 += u.y; a2 += u.z; a3 += u.w;
        }
        if (p1.x >= 0) {
            const float4 u = *(const float4*)&g_xn[(size_t)p1.x * DIN + lane * 4];
            a0 += u.x; a1 += u.y; a2 += u.z; a3 += u.w;
        }
        if (p2.x >= 0) {
            const float4 u = *(const float4*)&g_xn[(size_t)p2.x * DIN + lane * 4];
            a0 += u.x; a1 += u.y; a2 += u.z; a3 += u.w;
        }
        if (p3.x >= 0) {
            const float4 u = *(const float4*)&g_xn[(size_t)p3.x * DIN + lane * 4];
            a0 += u.x; a1 += u.y; a2 += u.z; a3 += u.w;
        }
        e0 = p0.y; e1 = p1.y; e2 = p2.y; e3 = p3.y;
    }
    const float di = rsqrtf(1.0f + (float)cnt);
    a0 *= di; a1 *= di; a2 *= di; a3 *= di;
    const __nv_bfloat162 h01 = __floats2bfloat162_rn(a0, a1);
    const __nv_bfloat162 h23 = __floats2bfloat162_rn(a2, a3);
    *(__nv_bfloat162*)&g_xs_h[nidx] = h01;
    *(__nv_bfloat162*)&g_xs_h[nidx + 2] = h23;
    *(__nv_bfloat162*)&g_xs_l[nidx] = __floats2bfloat162_rn(
        a0 - __bfloat162float(h01.x), a1 - __bfloat162float(h01.y));
    *(__nv_bfloat162*)&g_xs_l[nidx + 2] = __floats2bfloat162_rn(
        a2 - __bfloat162float(h23.x), a3 - __bfloat162float(h23.y));
}

// ---------------------------------------------------------------------------
// Launch
// ---------------------------------------------------------------------------
extern "C" void kernel_launch(void* const* d_in, const int* in_sizes, int n_in,
                              void* d_out, int out_size) {
    const float* x     = (const float*)d_in[0];
    const int*   ei    = (const int*)d_in[1];
    const float* W_gcn = (const float*)d_in[2];
    const float* b_gcn = (const float*)d_in[3];
    const float* W1    = (const float*)d_in[4];
    const float* b1    = (const float*)d_in[5];
    const float* W2    = (const float*)d_in[6];
    const float* b2    = (const float*)d_in[7];
    const float* W3    = (const float*)d_in[8];
    const float* b3    = (const float*)d_in[9];
    const float* Wout  = (const float*)d_in[10];
    const float* bout  = (const float*)d_in[11];
    float* out = (float*)d_out;

    const int N = in_sizes[0] / DIN;
    const int E = in_sizes[1] / 2;
    const int* src = ei;
    const int* dst = ei + E;

    bf16 *p_xs_h, *p_xs_l, *p_h1_h, *p_h1_l, *p_h2_h, *p_h2_l;
    bf16 *p_Wc_h, *p_Wc_l, *p_W2_h, *p_W2_l, *p_W3_h, *p_W3_l;
    float* p_bc;
    cudaGetSymbolAddress((void**)&p_xs_h, g_xs_h);
    cudaGetSymbolAddress((void**)&p_xs_l, g_xs_l);
    cudaGetSymbolAddress((void**)&p_h1_h, g_h1_h);
    cudaGetSymbolAddress((void**)&p_h1_l, g_h1_l);
    cudaGetSymbolAddress((void**)&p_h2_h, g_h2_h);
    cudaGetSymbolAddress((void**)&p_h2_l, g_h2_l);
    cudaGetSymbolAddress((void**)&p_Wc_h, g_Wc_h);
    cudaGetSymbolAddress((void**)&p_Wc_l, g_Wc_l);
    cudaGetSymbolAddress((void**)&p_W2_h, g_W2_h);
    cudaGetSymbolAddress((void**)&p_W2_l, g_W2_l);
    cudaGetSymbolAddress((void**)&p_W3_h, g_W3_h);
    cudaGetSymbolAddress((void**)&p_W3_l, g_W3_l);
    cudaGetSymbolAddress((void**)&p_bc, g_bc);

    const int SMEM = 98304;  // 3 stages x 32KB
    cudaFuncSetAttribute(mma_gemm<128, true, false>,
                         cudaFuncAttributeMaxDynamicSharedMemorySize, SMEM);
    cudaFuncSetAttribute(mma_gemm<256, true, false>,
                         cudaFuncAttributeMaxDynamicSharedMemorySize, SMEM);
    cudaFuncSetAttribute(mma_gemm<256, true, true>,
                         cudaFuncAttributeMaxDynamicSharedMemorySize, SMEM);

    // 1) fused prep: Wc/bc + W2/W3 split + out=b_out + heads/cnt init
    prep_fused<<<DIN + 1 + DIV_UP(PW1 + N, 256), 256>>>(
        W_gcn, W1, b_gcn, b1, W2, W3, bout, out, N);
    // 2) 4-chain bucket lists + degree counts (packed edges)
    scatter_ll<<<DIV_UP(E, 256), 256>>>(src, dst, E, N);
    // 3) xn = dinv * x
    xn_kernel<<<DIV_UP(N * 32, 256), 256>>>(x, N);
    // 4) xs = S @ x  (split bf16 output), warp per node
    agg_warp_kernel<<<DIV_UP(N * 32, 256), 256>>>(N);

    const int mt = DIV_UP(N, 128);
    const dim3 grid(HDIM / 128, mt);
    // 5) h1 = leaky(xs @ Wc + bc)
    mma_gemm<128, true, false><<<grid, 256, SMEM>>>(
        p_xs_h, p_xs_l, p_Wc_h, p_Wc_l, p_bc, p_h1_h, p_h1_l,
        nullptr, nullptr, HDIM, N);
    // 6) h2 = leaky(h1 @ W2 + b2)
    mma_gemm<256, true, false><<<grid, 256, SMEM>>>(
        p_h1_h, p_h1_l, p_W2_h, p_W2_l, b2, p_h2_h, p_h2_l,
        nullptr, nullptr, HDIM, N);
    // 7) out += leaky(h2 @ W3 + b3) . Wout   (fused)
    mma_gemm<256, true, true><<<grid, 256, SMEM>>>(
        p_h2_h, p_h2_l, p_W3_h, p_W3_l, b3, nullptr, nullptr,
        Wout, out, HDIM, N);
}